// round 13
// baseline (speedup 1.0000x reference)
#include <cuda_runtime.h>

// Problem dims (fixed)
#define T_  512
#define B_  256
#define F_  512
#define H_  128
#define G4_ 512   // 4*H
#define A_  8
#define MH_ 64

// Scratch (allocation-free rule: __device__ globals)
__device__ float g_xgates[(size_t)T_ * B_ * G4_];  // x @ W_ih^T + biases
__device__ float g_hseq[(size_t)T_ * B_ * H_];     // per-step hidden states

// ---------------------------------------------------------------------------
// Fast activations (fp32, ~1e-6 rel err)
// ---------------------------------------------------------------------------
__device__ __forceinline__ float sigm_f(float x) {
    return 1.0f / (1.0f + __expf(-x));
}
__device__ __forceinline__ float tanh_f(float x) {
    float e = __expf(2.0f * x);
    return 1.0f - 2.0f / (e + 1.0f);
}

// ---------------------------------------------------------------------------
// Kernel 1: xgates = X[131072,512] @ W_ih^T[512,512] + (b_ih + b_hh)
// 128x128x16 tiled SGEMM, double-buffered (unchanged from R10/R11).
// ---------------------------------------------------------------------------
#define KT 16
__global__ __launch_bounds__(256, 2)
void gemm_xw_kernel(const float* __restrict__ X,
                    const float* __restrict__ Wih,
                    const float* __restrict__ bih,
                    const float* __restrict__ bhh)
{
    __shared__ float As[2][KT * 128];
    __shared__ float Bs[2][KT * 128];

    const int tid = threadIdx.x;
    const int bm  = blockIdx.x >> 2;
    const int bn  = blockIdx.x & 3;
    const int m0  = bm * 128;
    const int g0  = bn * 128;

    const int tm = tid >> 4;
    const int tn = tid & 15;

    const int lrow = tid >> 1;
    const int lk   = (tid & 1) * 8;

    const float* Xp = X   + (size_t)(m0 + lrow) * F_ + lk;
    const float* Wp = Wih + (size_t)(g0 + lrow) * F_ + lk;

    float acc[8][8];
#pragma unroll
    for (int i = 0; i < 8; i++)
#pragma unroll
        for (int j = 0; j < 8; j++) acc[i][j] = 0.0f;

    float bias[8];
#pragma unroll
    for (int j = 0; j < 8; j++) {
        int g = g0 + tn * 8 + j;
        bias[j] = bih[g] + bhh[g];
    }

    float4 ra0 = *reinterpret_cast<const float4*>(Xp);
    float4 ra1 = *reinterpret_cast<const float4*>(Xp + 4);
    float4 rb0 = *reinterpret_cast<const float4*>(Wp);
    float4 rb1 = *reinterpret_cast<const float4*>(Wp + 4);
    {
        float av[8] = {ra0.x, ra0.y, ra0.z, ra0.w, ra1.x, ra1.y, ra1.z, ra1.w};
        float bv[8] = {rb0.x, rb0.y, rb0.z, rb0.w, rb1.x, rb1.y, rb1.z, rb1.w};
#pragma unroll
        for (int q = 0; q < 8; q++) {
            As[0][(lk + q) * 128 + lrow] = av[q];
            Bs[0][(lk + q) * 128 + lrow] = bv[q];
        }
    }
    __syncthreads();

    const int NT = F_ / KT;
#pragma unroll 1
    for (int kt = 0; kt < NT; kt++) {
        const int cur = kt & 1;

        if (kt + 1 < NT) {
            const float* xn = Xp + (kt + 1) * KT;
            const float* wn = Wp + (kt + 1) * KT;
            ra0 = *reinterpret_cast<const float4*>(xn);
            ra1 = *reinterpret_cast<const float4*>(xn + 4);
            rb0 = *reinterpret_cast<const float4*>(wn);
            rb1 = *reinterpret_cast<const float4*>(wn + 4);
        }

        const float* Ac = As[cur];
        const float* Bc = Bs[cur];
#pragma unroll
        for (int k = 0; k < KT; k++) {
            float a[8], b[8];
            float4 a0 = *reinterpret_cast<const float4*>(Ac + k * 128 + tm * 8);
            float4 a1 = *reinterpret_cast<const float4*>(Ac + k * 128 + tm * 8 + 4);
            float4 b0 = *reinterpret_cast<const float4*>(Bc + k * 128 + tn * 8);
            float4 b1 = *reinterpret_cast<const float4*>(Bc + k * 128 + tn * 8 + 4);
            a[0]=a0.x; a[1]=a0.y; a[2]=a0.z; a[3]=a0.w; a[4]=a1.x; a[5]=a1.y; a[6]=a1.z; a[7]=a1.w;
            b[0]=b0.x; b[1]=b0.y; b[2]=b0.z; b[3]=b0.w; b[4]=b1.x; b[5]=b1.y; b[6]=b1.z; b[7]=b1.w;
#pragma unroll
            for (int i = 0; i < 8; i++)
#pragma unroll
                for (int j = 0; j < 8; j++)
                    acc[i][j] = fmaf(a[i], b[j], acc[i][j]);
        }

        if (kt + 1 < NT) {
            const int nxt = cur ^ 1;
            float av[8] = {ra0.x, ra0.y, ra0.z, ra0.w, ra1.x, ra1.y, ra1.z, ra1.w};
            float bv[8] = {rb0.x, rb0.y, rb0.z, rb0.w, rb1.x, rb1.y, rb1.z, rb1.w};
#pragma unroll
            for (int q = 0; q < 8; q++) {
                As[nxt][(lk + q) * 128 + lrow] = av[q];
                Bs[nxt][(lk + q) * 128 + lrow] = bv[q];
            }
        }
        __syncthreads();
    }

#pragma unroll
    for (int i = 0; i < 8; i++) {
        int m = m0 + tm * 8 + i;
        float4 o0 = make_float4(acc[i][0] + bias[0], acc[i][1] + bias[1],
                                acc[i][2] + bias[2], acc[i][3] + bias[3]);
        float4 o1 = make_float4(acc[i][4] + bias[4], acc[i][5] + bias[5],
                                acc[i][6] + bias[6], acc[i][7] + bias[7]);
        float* dst = g_xgates + (size_t)m * G4_ + g0 + tn * 8;
        *reinterpret_cast<float4*>(dst)     = o0;
        *reinterpret_cast<float4*>(dst + 4) = o1;
    }
}

// ---------------------------------------------------------------------------
// Kernel 2: persistent masked-LSTM — GATE-LOCAL threads, ONE barrier/step.
// Grid = 128 blocks x 256 threads; block owns batch rows {2*bx, 2*bx+1}.
// Thread tid -> (col = tid>>1, bi = tid&1): computes ALL 4 gates
// {col, col+128, col+256, col+384} for its row. Gates never leave the
// thread: no gs exchange, Step B is register-local, h published via
// parity-double-buffered h rows -> a single __syncthreads per step.
// Lane pairing (row0,row1 adjacent) makes W smem reads 2-lane broadcast
// (W read exactly once per step) and h reads per-row broadcast.
// W_hh cols 0..KREG-1 in registers (4 gates x 48 = 192 regs), cols
// KREG..127 in smem.
//
// Dynamic smem (floats):
//   [0     , 40960) Wsm4 : float4[(q*20+k4)*128 + col] = W_hh[q*128+col][48+4k4..]
//   [40960 , 41984) done_s[1024]  (t-major, 2 rows)
//   [41984 , 42512) hbuf[2 parity][2 rows][132]  (132 pad: kills bank alias)
// total = 42512 floats = 170048 bytes
// ---------------------------------------------------------------------------
#define KREG 48
#define KR4  (KREG / 4)        // 12
#define KS4  ((H_ - KREG) / 4) // 20

__global__ __launch_bounds__(256, 1)
void lstm_kernel(const float* __restrict__ done,
                 const float* __restrict__ h0,
                 const float* __restrict__ c0,
                 const float* __restrict__ Whh,
                 float* __restrict__ hT,
                 float* __restrict__ cT)
{
    extern __shared__ float sm[];
    float4* Wsm4   = reinterpret_cast<float4*>(sm);   // [80*128] float4
    float*  done_s = sm + 40960;                      // [1024]
    float*  hbuf   = sm + 41984;                      // [2][2][132]

    const int tid = threadIdx.x;
    const int col = tid >> 1;     // 0..127
    const int bi  = tid & 1;      // row within pair
    const int b0  = blockIdx.x * 2;
    const int brow = b0 + bi;

    // Register W: rows {q*128+col}, cols 0..KREG-1 (both pair threads load same)
    float Wr[4][KREG];
#pragma unroll
    for (int q = 0; q < 4; q++) {
        const float4* wr = reinterpret_cast<const float4*>(Whh + (size_t)(q * 128 + col) * H_);
#pragma unroll
        for (int k4 = 0; k4 < KR4; k4++) {
            float4 v = wr[k4];
            Wr[q][4*k4+0] = v.x; Wr[q][4*k4+1] = v.y;
            Wr[q][4*k4+2] = v.z; Wr[q][4*k4+3] = v.w;
        }
        // smem W fill split between the pair: bi=0 -> q 0,1 ; bi=1 -> q 2,3
        if ((q >> 1) == bi) {
#pragma unroll
            for (int k4 = 0; k4 < KS4; k4++)
                Wsm4[(q * KS4 + k4) * 128 + col] = wr[KR4 + k4];
        }
    }
    // done-mask preload (t-major, 2 rows)
    for (int idx = tid; idx < 2 * T_; idx += 256) {
        int t = idx >> 1, bi2 = idx & 1;
        done_s[idx] = done[(size_t)t * B_ + b0 + bi2];
    }

    // init state; mask for t=0 and publish h into parity 0
    float creg, hreg;
    {
        // need done_s visible — but done_s[bi] is loaded by threads 0/1 only;
        // read done directly for init (cheap, once)
        float m = 1.0f - done[(size_t)0 * B_ + brow];
        hreg = h0[(size_t)brow * H_ + col];
        creg = c0[(size_t)brow * H_ + col];
        creg *= m;
        hbuf[0 * 264 + bi * 132 + col] = hreg * m;
    }
    __syncthreads();

    // xg for current step (4 gates), prefetched one step ahead
    const size_t step_stride = (size_t)B_ * G4_;
    const float* xg_row = g_xgates + (size_t)brow * G4_;
    float xg[4];
#pragma unroll
    for (int q = 0; q < 4; q++) xg[q] = xg_row[q * 128 + col];

    float hfin = 0.0f, cfin = 0.0f;

#pragma unroll 1
    for (int t = 0; t < T_; t++) {
        const int par = t & 1;
        const float4* hv = reinterpret_cast<const float4*>(hbuf + par * 264 + bi * 132);

        // prefetch next step's xg
        const int tnx = (t + 1 < T_) ? (t + 1) : t;
        const float* xn = xg_row + (size_t)tnx * step_stride;
        float nx[4];
#pragma unroll
        for (int q = 0; q < 4; q++) nx[q] = xn[q * 128 + col];

        // ---- 4 gate dot products over this thread's row
        float a0 = 0.0f, e0 = 0.0f, a1 = 0.0f, e1 = 0.0f;
        float a2 = 0.0f, e2 = 0.0f, a3 = 0.0f, e3 = 0.0f;

        // register-W part (cols 0..KREG-1)
#pragma unroll
        for (int k4 = 0; k4 < KR4; k4++) {
            float4 h4 = hv[k4];
            a0 = fmaf(Wr[0][4*k4+0], h4.x, a0);
            e0 = fmaf(Wr[0][4*k4+1], h4.y, e0);
            a0 = fmaf(Wr[0][4*k4+2], h4.z, a0);
            e0 = fmaf(Wr[0][4*k4+3], h4.w, e0);
            a1 = fmaf(Wr[1][4*k4+0], h4.x, a1);
            e1 = fmaf(Wr[1][4*k4+1], h4.y, e1);
            a1 = fmaf(Wr[1][4*k4+2], h4.z, a1);
            e1 = fmaf(Wr[1][4*k4+3], h4.w, e1);
            a2 = fmaf(Wr[2][4*k4+0], h4.x, a2);
            e2 = fmaf(Wr[2][4*k4+1], h4.y, e2);
            a2 = fmaf(Wr[2][4*k4+2], h4.z, a2);
            e2 = fmaf(Wr[2][4*k4+3], h4.w, e2);
            a3 = fmaf(Wr[3][4*k4+0], h4.x, a3);
            e3 = fmaf(Wr[3][4*k4+1], h4.y, e3);
            a3 = fmaf(Wr[3][4*k4+2], h4.z, a3);
            e3 = fmaf(Wr[3][4*k4+3], h4.w, e3);
        }
        // smem-W part (cols KREG..127)
#pragma unroll 4
        for (int k4 = 0; k4 < KS4; k4++) {
            float4 h4 = hv[KR4 + k4];
            float4 w0 = Wsm4[(0 * KS4 + k4) * 128 + col];
            float4 w1 = Wsm4[(1 * KS4 + k4) * 128 + col];
            float4 w2 = Wsm4[(2 * KS4 + k4) * 128 + col];
            float4 w3 = Wsm4[(3 * KS4 + k4) * 128 + col];
            a0 = fmaf(w0.x, h4.x, a0);
            e0 = fmaf(w0.y, h4.y, e0);
            a0 = fmaf(w0.z, h4.z, a0);
            e0 = fmaf(w0.w, h4.w, e0);
            a1 = fmaf(w1.x, h4.x, a1);
            e1 = fmaf(w1.y, h4.y, e1);
            a1 = fmaf(w1.z, h4.z, a1);
            e1 = fmaf(w1.w, h4.w, e1);
            a2 = fmaf(w2.x, h4.x, a2);
            e2 = fmaf(w2.y, h4.y, e2);
            a2 = fmaf(w2.z, h4.z, a2);
            e2 = fmaf(w2.w, h4.w, e2);
            a3 = fmaf(w3.x, h4.x, a3);
            e3 = fmaf(w3.y, h4.y, e3);
            a3 = fmaf(w3.z, h4.z, a3);
            e3 = fmaf(w3.w, h4.w, e3);
        }

        // ---- gate-local nonlinearities + state update (no exchange!)
        float gi = a0 + e0 + xg[0];
        float gf = a1 + e1 + xg[1];
        float gg = a2 + e2 + xg[2];
        float go = a3 + e3 + xg[3];

        xg[0] = nx[0]; xg[1] = nx[1]; xg[2] = nx[2]; xg[3] = nx[3];

        float iv = sigm_f(gi);
        float fv = sigm_f(gf);
        float gv = tanh_f(gg);
        float ov = sigm_f(go);
        creg = fmaf(fv, creg, iv * gv);
        float hv_ = ov * tanh_f(creg);
        g_hseq[((size_t)t * B_ + brow) * H_ + col] = hv_;

        if (t + 1 < T_) {
            float m = 1.0f - done_s[(t + 1) * 2 + bi];
            creg *= m;
            hbuf[(par ^ 1) * 264 + bi * 132 + col] = hv_ * m;
        } else {
            hfin = hv_;
            cfin = creg;
        }
        __syncthreads();   // single barrier: h(t+1) published for all
    }

    hT[(size_t)brow * H_ + col] = hfin;
    cT[(size_t)brow * H_ + col] = cfin;
}

// ---------------------------------------------------------------------------
// Kernel 3: heads (unchanged, known good).
// ---------------------------------------------------------------------------
__global__ __launch_bounds__(256, 1)
void heads_kernel(const float* __restrict__ Wp1, const float* __restrict__ bp1,
                  const float* __restrict__ Wp2, const float* __restrict__ bp2,
                  const float* __restrict__ Wv1, const float* __restrict__ bv1,
                  const float* __restrict__ Wv2, const float* __restrict__ bv2,
                  float* __restrict__ out)
{
    extern __shared__ float sm[];
    float* h_s  = sm;            // [256][129]
    float* wp1  = sm + 33024;
    float* wv1  = sm + 41216;
    float* wp2  = sm + 49408;
    float* wv2  = sm + 49920;
    float* sbp1 = sm + 49984;
    float* sbv1 = sm + 50048;

    const int tid = threadIdx.x;
    const size_t row0 = (size_t)blockIdx.x * 256;

    for (int idx = tid; idx < 256 * 32; idx += 256) {
        int r  = idx >> 5;
        int c4 = idx & 31;
        float4 v = reinterpret_cast<const float4*>(g_hseq + (row0 + r) * H_)[c4];
        float* dst = h_s + r * 129 + c4 * 4;
        dst[0] = v.x; dst[1] = v.y; dst[2] = v.z; dst[3] = v.w;
    }
    for (int idx = tid; idx < H_ * MH_; idx += 256) {
        wp1[idx] = Wp1[idx];
        wv1[idx] = Wv1[idx];
    }
    for (int idx = tid; idx < MH_ * A_; idx += 256) wp2[idx] = Wp2[idx];
    if (tid < 64) {
        wv2[tid]  = Wv2[tid];
        sbp1[tid] = bp1[tid];
        sbv1[tid] = bv1[tid];
    }
    __syncthreads();

    float ap[64], av[64];
#pragma unroll
    for (int i = 0; i < 64; i++) { ap[i] = 0.0f; av[i] = 0.0f; }

    const float*  hrow = h_s + tid * 129;
    const float4* wp1v = reinterpret_cast<const float4*>(wp1);
    const float4* wv1v = reinterpret_cast<const float4*>(wv1);

#pragma unroll 1
    for (int k = 0; k < H_; k++) {
        float hk = hrow[k];
#pragma unroll
        for (int m4 = 0; m4 < 16; m4++) {
            float4 wp = wp1v[k * 16 + m4];
            float4 wv = wv1v[k * 16 + m4];
            ap[m4 * 4 + 0] = fmaf(hk, wp.x, ap[m4 * 4 + 0]);
            ap[m4 * 4 + 1] = fmaf(hk, wp.y, ap[m4 * 4 + 1]);
            ap[m4 * 4 + 2] = fmaf(hk, wp.z, ap[m4 * 4 + 2]);
            ap[m4 * 4 + 3] = fmaf(hk, wp.w, ap[m4 * 4 + 3]);
            av[m4 * 4 + 0] = fmaf(hk, wv.x, av[m4 * 4 + 0]);
            av[m4 * 4 + 1] = fmaf(hk, wv.y, av[m4 * 4 + 1]);
            av[m4 * 4 + 2] = fmaf(hk, wv.z, av[m4 * 4 + 2]);
            av[m4 * 4 + 3] = fmaf(hk, wv.w, av[m4 * 4 + 3]);
        }
    }

    float lg[8];
#pragma unroll
    for (int a = 0; a < 8; a++) lg[a] = bp2[a];
    float v = bv2[0];

#pragma unroll
    for (int mh = 0; mh < 64; mh++) {
        float tp = tanh_f(ap[mh] + sbp1[mh]);
        float tv = tanh_f(av[mh] + sbv1[mh]);
        v = fmaf(tv, wv2[mh], v);
#pragma unroll
        for (int a = 0; a < 8; a++)
            lg[a] = fmaf(tp, wp2[mh * 8 + a], lg[a]);
    }

    float* orow = out + (row0 + tid) * 9;
#pragma unroll
    for (int a = 0; a < 8; a++) orow[a] = lg[a];
    orow[8] = v;
}

// ---------------------------------------------------------------------------
// Launch
// ---------------------------------------------------------------------------
extern "C" void kernel_launch(void* const* d_in, const int* in_sizes, int n_in,
                              void* d_out, int out_size)
{
    (void)in_sizes; (void)n_in; (void)out_size;

    const float* x    = (const float*)d_in[0];
    const float* done = (const float*)d_in[1];
    const float* h0   = (const float*)d_in[2];
    const float* c0   = (const float*)d_in[3];
    const float* Wih  = (const float*)d_in[4];
    const float* Whh  = (const float*)d_in[5];
    const float* bih  = (const float*)d_in[6];
    const float* bhh  = (const float*)d_in[7];
    const float* Wp1  = (const float*)d_in[8];
    const float* bp1  = (const float*)d_in[9];
    const float* Wp2  = (const float*)d_in[10];
    const float* bp2  = (const float*)d_in[11];
    const float* Wv1  = (const float*)d_in[12];
    const float* bv1  = (const float*)d_in[13];
    const float* Wv2  = (const float*)d_in[14];
    const float* bv2  = (const float*)d_in[15];

    float* out = (float*)d_out;
    float* hT  = out + (size_t)T_ * B_ * (A_ + 1);   // after [T*B, 9]
    float* cT  = hT + (size_t)B_ * H_;

    const int lstm_smem  = 42512 * 4;   // 170048 B
    const int heads_smem = 50112 * 4;   // 200448 B
    cudaFuncSetAttribute(lstm_kernel,  cudaFuncAttributeMaxDynamicSharedMemorySize, lstm_smem);
    cudaFuncSetAttribute(heads_kernel, cudaFuncAttributeMaxDynamicSharedMemorySize, heads_smem);

    // 1) input projection: 1024 m-tiles x 4 n-tiles (double-buffered)
    gemm_xw_kernel<<<4096, 256>>>(x, Wih, bih, bhh);
    // 2) recurrence: 128 persistent blocks, gate-local threads, 1 barrier/step
    lstm_kernel<<<128, 256, lstm_smem>>>(done, h0, c0, Whh, hT, cT);
    // 3) heads: 512 blocks x 256 rows
    heads_kernel<<<512, 256, heads_smem>>>(Wp1, bp1, Wp2, bp2, Wv1, bv1, Wv2, bv2, out);
}